// round 1
// baseline (speedup 1.0000x reference)
#include <cuda_runtime.h>
#include <cstdint>

// ---------------------------------------------------------------------------
// DivTree: x1 = relu(x0 @ Wsh + bsh)            (131072 x 512) @ (512 x 512)
//          h  = relu(x1[:,a,:] @ W1[route[a]])  32 x (4096 x 512) @ (512 x 512)
//          y  = h[:,a,:] @ W2[route[a]] + b2    32 x (4096 x 512) @ (512 x 32)
// TF32 mma.sync (m16n8k8), cp.async double-buffered, fused bias+relu epilogue.
// ---------------------------------------------------------------------------

// Scratch for intermediates (allocation-free rule: __device__ globals).
__device__ float g_x1[67108864];  // 4096*32*512
__device__ float g_h [67108864];  // 4096*32*512

__device__ __forceinline__ unsigned f2tf32(float x) {
    unsigned r;
    asm("cvt.rna.tf32.f32 %0, %1;" : "=r"(r) : "f"(x));
    return r;
}

__device__ __forceinline__ void cp_async16(uint32_t dst, const void* src) {
    asm volatile("cp.async.cg.shared.global [%0], [%1], 16;\n" :: "r"(dst), "l"(src));
}
__device__ __forceinline__ void cp_commit() { asm volatile("cp.async.commit_group;\n"); }
__device__ __forceinline__ void cp_wait0()  { asm volatile("cp.async.wait_group 0;\n"); }

__device__ __forceinline__ void mma_tf32(float* c, const unsigned* a, const unsigned* b) {
    asm volatile(
        "mma.sync.aligned.m16n8k8.row.col.f32.tf32.tf32.f32 "
        "{%0,%1,%2,%3}, {%4,%5,%6,%7}, {%8,%9}, {%0,%1,%2,%3};\n"
        : "+f"(c[0]), "+f"(c[1]), "+f"(c[2]), "+f"(c[3])
        : "r"(a[0]), "r"(a[1]), "r"(a[2]), "r"(a[3]), "r"(b[0]), "r"(b[1]));
}

// Generic strided-row TF32 GEMM:  C[m,n] = act( sum_k A[m,k]*W[k,n] + bias[n] )
//   A rows at Ap + m*lda (Ap = Abase + agent*aStride)
//   W (K x N) row-major; per-agent gather: W += route[agent]*K*N
//   C rows at Cp + m*ldc (Cp = Cbase + agent*cStride)
// Grid: (N/BN, M/BM, n_agents). All dims divide tiles exactly.
template<int BM, int BN, int BK, int WM, int WN, bool RELU, bool GATHER>
__global__ void __launch_bounds__(256)
gemm_tf32_kernel(const float* __restrict__ Abase, long aStride, int lda,
                 const float* __restrict__ Wbase, const float* __restrict__ biasBase,
                 const int* __restrict__ route,
                 float* __restrict__ Cbase, long cStride, int ldc,
                 int N, int K)
{
    constexpr int WARPS_M = BM / WM;
    constexpr int WARPS_N = BN / WN;
    constexpr int THREADS = WARPS_M * WARPS_N * 32;
    static_assert(THREADS == 256, "block size mismatch");
    constexpr int MI = WM / 16;
    constexpr int NI = WN / 8;
    constexpr int APAD = 4;  // A row stride BK+4: 20 / 36 floats -> conflict-free frag loads
    constexpr int BPAD = 8;  // B row stride BN+8: 136 / 40 floats -> conflict-free frag loads

    __shared__ float As[2][BM][BK + APAD];
    __shared__ float Bs[2][BK][BN + BPAD];

    const int tid  = threadIdx.x;
    const int lane = tid & 31;
    const int warp = tid >> 5;
    const int warp_m = warp / WARPS_N;
    const int warp_n = warp % WARPS_N;
    const int g  = lane >> 2;   // group id 0..7
    const int tg = lane & 3;    // thread-in-group 0..3

    const int agent = blockIdx.z;
    const float* Ap = Abase + (size_t)agent * (size_t)aStride;
    const float* Wp;
    const float* biasp;
    if (GATHER) {
        const int e = __ldg(&route[agent]);
        Wp    = Wbase    + (size_t)e * (size_t)K * (size_t)N;
        biasp = biasBase + (size_t)e * (size_t)N;
    } else {
        Wp = Wbase;
        biasp = biasBase;
    }
    float* Cp = Cbase + (size_t)agent * (size_t)cStride;

    const int m0 = blockIdx.y * BM;
    const int n0 = blockIdx.x * BN;

    float acc[MI][NI][4];
    #pragma unroll
    for (int mi = 0; mi < MI; ++mi)
        #pragma unroll
        for (int ni = 0; ni < NI; ++ni)
            #pragma unroll
            for (int r = 0; r < 4; ++r) acc[mi][ni][r] = 0.0f;

    auto load_stage = [&](int buf, int k0) {
        constexpr int ACH = BM * (BK / 4);   // 16B chunks in A tile
        #pragma unroll
        for (int i = 0; i < ACH; i += THREADS) {
            const int idx = i + tid;
            const int r = idx / (BK / 4);
            const int c = (idx % (BK / 4)) * 4;
            cp_async16((uint32_t)__cvta_generic_to_shared(&As[buf][r][c]),
                       Ap + (size_t)(m0 + r) * (size_t)lda + k0 + c);
        }
        constexpr int BCH = BK * (BN / 4);   // 16B chunks in B tile
        #pragma unroll
        for (int i = 0; i < BCH; i += THREADS) {
            const int idx = i + tid;
            const int r = idx / (BN / 4);
            const int c = (idx % (BN / 4)) * 4;
            cp_async16((uint32_t)__cvta_generic_to_shared(&Bs[buf][r][c]),
                       Wp + (size_t)(k0 + r) * (size_t)N + n0 + c);
        }
    };

    const int KT = K / BK;
    load_stage(0, 0);
    cp_commit();

    for (int kt = 0; kt < KT; ++kt) {
        const int cur = kt & 1;
        cp_wait0();
        __syncthreads();
        if (kt + 1 < KT) { load_stage(cur ^ 1, (kt + 1) * BK); cp_commit(); }

        #pragma unroll
        for (int kk = 0; kk < BK; kk += 8) {
            unsigned af[MI][4];
            unsigned bf[NI][2];
            #pragma unroll
            for (int mi = 0; mi < MI; ++mi) {
                const int r = warp_m * WM + mi * 16 + g;
                af[mi][0] = f2tf32(As[cur][r    ][kk + tg    ]);
                af[mi][1] = f2tf32(As[cur][r + 8][kk + tg    ]);
                af[mi][2] = f2tf32(As[cur][r    ][kk + tg + 4]);
                af[mi][3] = f2tf32(As[cur][r + 8][kk + tg + 4]);
            }
            #pragma unroll
            for (int ni = 0; ni < NI; ++ni) {
                const int cn = warp_n * WN + ni * 8 + g;
                bf[ni][0] = f2tf32(Bs[cur][kk + tg    ][cn]);
                bf[ni][1] = f2tf32(Bs[cur][kk + tg + 4][cn]);
            }
            #pragma unroll
            for (int mi = 0; mi < MI; ++mi)
                #pragma unroll
                for (int ni = 0; ni < NI; ++ni)
                    mma_tf32(acc[mi][ni], af[mi], bf[ni]);
        }
    }

    // Epilogue: bias + optional relu, float2 stores.
    #pragma unroll
    for (int mi = 0; mi < MI; ++mi) {
        #pragma unroll
        for (int ni = 0; ni < NI; ++ni) {
            const int r  = m0 + warp_m * WM + mi * 16 + g;
            const int cn = n0 + warp_n * WN + ni * 8 + tg * 2;
            const float b0 = biasp[cn];
            const float b1 = biasp[cn + 1];
            float v0 = acc[mi][ni][0] + b0;
            float v1 = acc[mi][ni][1] + b1;
            float v2 = acc[mi][ni][2] + b0;
            float v3 = acc[mi][ni][3] + b1;
            if (RELU) {
                v0 = fmaxf(v0, 0.0f); v1 = fmaxf(v1, 0.0f);
                v2 = fmaxf(v2, 0.0f); v3 = fmaxf(v3, 0.0f);
            }
            *(float2*)&Cp[(size_t)r * (size_t)ldc + cn]       = make_float2(v0, v1);
            *(float2*)&Cp[(size_t)(r + 8) * (size_t)ldc + cn] = make_float2(v2, v3);
        }
    }
}

extern "C" void kernel_launch(void* const* d_in, const int* in_sizes, int n_in,
                              void* d_out, int out_size) {
    (void)in_sizes; (void)n_in; (void)out_size;
    const float* x0  = (const float*)d_in[0];   // (4096, 32, 512)
    const float* Wsh = (const float*)d_in[1];   // (512, 512)
    const float* bsh = (const float*)d_in[2];   // (512,)
    const float* W1  = (const float*)d_in[3];   // (32, 512, 512)
    const float* b1  = (const float*)d_in[4];   // (32, 512)
    const float* W2  = (const float*)d_in[5];   // (32, 512, 32)
    const float* b2  = (const float*)d_in[6];   // (32, 32)
    const int*   route = (const int*)d_in[7];   // (32,)
    float* out = (float*)d_out;                 // (4096, 32, 32)

    float* x1 = nullptr;
    float* h  = nullptr;
    cudaGetSymbolAddress((void**)&x1, g_x1);
    cudaGetSymbolAddress((void**)&h,  g_h);

    dim3 blk(256);

    // GEMM1: x1 = relu(x0 @ Wsh + bsh); flattened M=131072, N=512, K=512
    gemm_tf32_kernel<128, 128, 16, 32, 64, true, false>
        <<<dim3(512 / 128, 131072 / 128, 1), blk>>>(
            x0, 0, 512, Wsh, bsh, nullptr, x1, 0, 512, 512, 512);

    // GEMM2 (per agent): h[:,a,:] = relu(x1[:,a,:] @ W1[route[a]] + b1[route[a]])
    // A rows strided by 32*512; per-agent base offset a*512.
    gemm_tf32_kernel<128, 128, 16, 32, 64, true, true>
        <<<dim3(512 / 128, 4096 / 128, 32), blk>>>(
            x1, 512, 32 * 512, W1, b1, route, h, 512, 32 * 512, 512, 512);

    // GEMM3 (per agent): y[:,a,:] = h[:,a,:] @ W2[route[a]] + b2[route[a]]
    gemm_tf32_kernel<128, 32, 32, 16, 32, false, true>
        <<<dim3(32 / 32, 4096 / 128, 32), blk>>>(
            h, 512, 32 * 512, W2, b2, route, out, 32, 32 * 32, 32, 512);
}

// round 3
// speedup vs baseline: 2.0618x; 2.0618x over previous
#include <cuda_runtime.h>
#include <cuda_fp16.h>
#include <cstdint>

// ---------------------------------------------------------------------------
// DivTree via fp16 mma.sync.m16n8k16 (f32 accum) + ldmatrix + cp.async 3-stage.
//   pre: x0h = fp16(x0); WT* = transpose+fp16(W) (K-major B operands)
//   L1: x1h = relu(x0 @ Wsh + bsh)            (131072 x 512) @ (512 x 512)
//   L2: hh  = relu(x1[:,a,:] @ W1[r[a]] + b1) 32 x (4096 x 512) @ (512 x 512)
//   L3: y   = h[:,a,:] @ W2[r[a]] + b2        32 x (4096 x 512) @ (512 x 32)
// fp16 eps == tf32 eps (2^-11); round-1 tf32 measured rel_err 5.06e-4.
// ---------------------------------------------------------------------------

// Scratch (allocation-free rule: __device__ globals).
__device__ __half g_x0h[67108864];   // 4096*32*512
__device__ __half g_x1h[67108864];
__device__ __half g_hh [67108864];
__device__ __half g_wshT[262144];    // 512*512
__device__ __half g_w1T[8388608];    // 32*512*512
__device__ __half g_w2T[524288];     // 32*32*512

// ----------------------------- PTX helpers --------------------------------
__device__ __forceinline__ uint32_t smem_u32(const void* p) {
    uint32_t a;
    asm("{ .reg .u64 t; cvta.to.shared.u64 t, %1; cvt.u32.u64 %0, t; }"
        : "=r"(a) : "l"(p));
    return a;
}
__device__ __forceinline__ void cp_async16(uint32_t dst, const void* src) {
    asm volatile("cp.async.cg.shared.global [%0], [%1], 16;\n" :: "r"(dst), "l"(src));
}
__device__ __forceinline__ void cp_commit() { asm volatile("cp.async.commit_group;\n"); }
template<int N>
__device__ __forceinline__ void cp_wait_group() {
    asm volatile("cp.async.wait_group %0;\n" :: "n"(N));
}
__device__ __forceinline__ void ldsm_x4(uint32_t* r, uint32_t addr) {
    asm volatile("ldmatrix.sync.aligned.m8n8.x4.shared.b16 {%0,%1,%2,%3}, [%4];"
                 : "=r"(r[0]), "=r"(r[1]), "=r"(r[2]), "=r"(r[3]) : "r"(addr));
}
__device__ __forceinline__ void mma_f16(float* c, const uint32_t* a, const uint32_t* b) {
    asm volatile(
        "mma.sync.aligned.m16n8k16.row.col.f32.f16.f16.f32 "
        "{%0,%1,%2,%3}, {%4,%5,%6,%7}, {%8,%9}, {%0,%1,%2,%3};\n"
        : "+f"(c[0]), "+f"(c[1]), "+f"(c[2]), "+f"(c[3])
        : "r"(a[0]), "r"(a[1]), "r"(a[2]), "r"(a[3]), "r"(b[0]), "r"(b[1]));
}

// ---------------------- elementwise f32 -> f16 (x0) ------------------------
// n multiple of 8; each thread converts 8 elements.
__global__ void cvt_f32_f16_kernel(const float* __restrict__ in, __half* __restrict__ out,
                                   int n8) {
    const int i = blockIdx.x * blockDim.x + threadIdx.x;
    if (i >= n8) return;
    const float4 f0 = ((const float4*)in)[2 * i];
    const float4 f1 = ((const float4*)in)[2 * i + 1];
    __half2 h[4];
    h[0] = __floats2half2_rn(f0.x, f0.y);
    h[1] = __floats2half2_rn(f0.z, f0.w);
    h[2] = __floats2half2_rn(f1.x, f1.y);
    h[3] = __floats2half2_rn(f1.z, f1.w);
    ((uint4*)out)[i] = *(uint4*)h;
}

// ------------------- transpose + cvt weights to fp16 -----------------------
// WT[e][n][k] = (half)W[e][k][n]; K, N multiples of 32. block (32,8).
__global__ void transpose_h_kernel(const float* __restrict__ W, __half* __restrict__ WT,
                                   int K, int N) {
    __shared__ float t[32][33];
    const int e  = blockIdx.z;
    const int k0 = blockIdx.y * 32;
    const int n0 = blockIdx.x * 32;
    const float* Wp  = W  + (size_t)e * (size_t)K * (size_t)N;
    __half*      WTp = WT + (size_t)e * (size_t)K * (size_t)N;
    const int tx = threadIdx.x, ty = threadIdx.y;
    #pragma unroll
    for (int i = 0; i < 32; i += 8)
        t[ty + i][tx] = Wp[(size_t)(k0 + ty + i) * N + n0 + tx];
    __syncthreads();
    #pragma unroll
    for (int i = 0; i < 32; i += 8)
        WTp[(size_t)(n0 + ty + i) * K + k0 + tx] = __float2half_rn(t[tx][ty + i]);
}

// ----------------------------- fp16 GEMM -----------------------------------
// C[m,n] = act( sum_k A[m,k] * BT[n,k] + bias[n] ), A/BT fp16, C fp16 or f32.
//   A rows at Ap + m*lda (Ap = Abase + agent*aStride), lda in halves
//   BT is [N][K] K-major fp16; gather: += route[z]*Nfull*K
// BK = 64 halves (128B rows, SW128 swizzle). Grid: (Nfull/BN, M/BM, agents).
template<int BM, int BN, int WM, int WN, int THREADS, int STAGES,
         bool RELU, bool GATHER, bool OUT_HALF>
__global__ void __launch_bounds__(THREADS, 1)
hgemm(const __half* __restrict__ Abase, long aStride, int lda,
      const __half* __restrict__ BTbase, const float* __restrict__ biasBase,
      const int* __restrict__ route,
      void* __restrict__ Cbase, long cStride, int ldc,
      int Nfull, int K)
{
    constexpr int BK = 64;                   // halves per k-stage (128 bytes)
    constexpr int WARPS_N = BN / WN;
    constexpr int MI = WM / 16;
    constexpr int NI = WN / 8;
    constexpr int NP = NI / 2;               // ldmatrix x4 covers 2 n8 frags
    constexpr int STAGE = (BM + BN) * 128;   // bytes per stage

    extern __shared__ char smraw[];
    char* sm = (char*)(((uintptr_t)smraw + 127) & ~(uintptr_t)127);

    const int tid  = threadIdx.x;
    const int lane = tid & 31;
    const int warp = tid >> 5;
    const int warp_m = warp / WARPS_N;
    const int warp_n = warp % WARPS_N;
    const int g  = lane >> 2;
    const int tg = lane & 3;

    const uint32_t aBuf0 = smem_u32(sm);
    const uint32_t bBuf0 = aBuf0 + BM * 128;

    const int agent = blockIdx.z;
    const __half* Ap = Abase + (size_t)agent * (size_t)aStride;
    const __half* Bp;
    const float* biasp;
    if (GATHER) {
        const int e = __ldg(&route[agent]);
        Bp    = BTbase   + (size_t)e * (size_t)Nfull * (size_t)K;
        biasp = biasBase + (size_t)e * (size_t)Nfull;
    } else {
        Bp = BTbase; biasp = biasBase;
    }

    const int m0 = blockIdx.y * BM;
    const int n0 = blockIdx.x * BN;

    // ldmatrix per-lane base addresses (stage 0; add s*STAGE at use).
    // A frag (m16k16): lanes 0-15 -> rows (lane&15), lanes 16-31 -> same rows,
    // second 16B chunk. addr = rowbase + ((2ks + hb)<<4 ^ xor)
    uint32_t aAddr[MI], aXor[MI];
    {
        const int rr = warp_m * WM + (lane & 15);
        #pragma unroll
        for (int mi = 0; mi < MI; ++mi) {
            const int r = rr + mi * 16;
            aAddr[mi] = aBuf0 + r * 128;
            aXor[mi]  = (uint32_t)(r & 7) << 4;
        }
    }
    const uint32_t a_hb = (uint32_t)(lane >> 4);
    // B frags (two n8k16 per x4): rows (lane&7) + ((lane>>4)<<3), chunk +((lane>>3)&1)
    uint32_t bAddr[NP], bXor[NP];
    {
        const int rr = warp_n * WN + (lane & 7) + ((lane >> 4) << 3);
        #pragma unroll
        for (int p = 0; p < NP; ++p) {
            const int r = rr + p * 16;
            bAddr[p] = bBuf0 + r * 128;
            bXor[p]  = (uint32_t)(r & 7) << 4;
        }
    }
    const uint32_t b_cadd = (uint32_t)((lane >> 3) & 1);

    float acc[MI][NI][4];
    #pragma unroll
    for (int mi = 0; mi < MI; ++mi)
        #pragma unroll
        for (int ni = 0; ni < NI; ++ni)
            #pragma unroll
            for (int r = 0; r < 4; ++r) acc[mi][ni][r] = 0.0f;

    auto load_stage = [&](int s, int k0) {
        const uint32_t aD = aBuf0 + s * STAGE;
        const uint32_t bD = bBuf0 + s * STAGE;
        #pragma unroll
        for (int i = 0; i < BM * 8; i += THREADS) {
            const int idx = i + tid;
            const int r = idx >> 3, c = idx & 7;
            cp_async16(aD + r * 128 + (((uint32_t)(c ^ (r & 7))) << 4),
                       Ap + (size_t)(m0 + r) * (size_t)lda + k0 + c * 8);
        }
        #pragma unroll
        for (int i = 0; i < BN * 8; i += THREADS) {
            const int idx = i + tid;
            const int r = idx >> 3, c = idx & 7;
            cp_async16(bD + r * 128 + (((uint32_t)(c ^ (r & 7))) << 4),
                       Bp + (size_t)(n0 + r) * (size_t)K + k0 + c * 8);
        }
        cp_commit();
    };

    const int KT = K / BK;

    #pragma unroll
    for (int s = 0; s < STAGES - 1; ++s) load_stage(s, s * BK);

    for (int kt = 0; kt < KT; ++kt) {
        cp_wait_group<STAGES - 2>();
        __syncthreads();

        const int nk = kt + STAGES - 1;
        if (nk < KT) load_stage(nk % STAGES, nk * BK);
        else cp_commit();                      // keep group count uniform

        const uint32_t sOff = (uint32_t)((kt % STAGES) * STAGE);
        #pragma unroll
        for (int ks = 0; ks < BK / 16; ++ks) {
            uint32_t af[MI][4], bf[NP][4];
            #pragma unroll
            for (int mi = 0; mi < MI; ++mi)
                ldsm_x4(af[mi], aAddr[mi] + sOff +
                        ((((uint32_t)(2 * ks) + a_hb) << 4) ^ aXor[mi]));
            #pragma unroll
            for (int p = 0; p < NP; ++p)
                ldsm_x4(bf[p], bAddr[p] + sOff +
                        ((((uint32_t)(2 * ks) + b_cadd) << 4) ^ bXor[p]));
            #pragma unroll
            for (int mi = 0; mi < MI; ++mi)
                #pragma unroll
                for (int ni = 0; ni < NI; ++ni)
                    mma_f16(acc[mi][ni], af[mi], &bf[ni >> 1][(ni & 1) * 2]);
        }
    }

    // Epilogue: bias + optional relu; fp16 or f32 stores.
    #pragma unroll
    for (int mi = 0; mi < MI; ++mi) {
        #pragma unroll
        for (int ni = 0; ni < NI; ++ni) {
            const int r  = m0 + warp_m * WM + mi * 16 + g;
            const int cn = n0 + warp_n * WN + ni * 8 + tg * 2;
            const float2 bv = *(const float2*)&biasp[cn];
            float v0 = acc[mi][ni][0] + bv.x;
            float v1 = acc[mi][ni][1] + bv.y;
            float v2 = acc[mi][ni][2] + bv.x;
            float v3 = acc[mi][ni][3] + bv.y;
            if (RELU) {
                v0 = fmaxf(v0, 0.f); v1 = fmaxf(v1, 0.f);
                v2 = fmaxf(v2, 0.f); v3 = fmaxf(v3, 0.f);
            }
            const size_t ag = (size_t)agent * (size_t)cStride;
            if (OUT_HALF) {
                __half* C = (__half*)Cbase + ag;
                *(__half2*)&C[(size_t)r * ldc + cn]       = __floats2half2_rn(v0, v1);
                *(__half2*)&C[(size_t)(r + 8) * ldc + cn] = __floats2half2_rn(v2, v3);
            } else {
                float* C = (float*)Cbase + ag;
                *(float2*)&C[(size_t)r * ldc + cn]       = make_float2(v0, v1);
                *(float2*)&C[(size_t)(r + 8) * ldc + cn] = make_float2(v2, v3);
            }
        }
    }
}

// ------------------------------- launch ------------------------------------
extern "C" void kernel_launch(void* const* d_in, const int* in_sizes, int n_in,
                              void* d_out, int out_size) {
    (void)in_sizes; (void)n_in; (void)out_size;
    const float* x0  = (const float*)d_in[0];   // (4096, 32, 512)
    const float* Wsh = (const float*)d_in[1];   // (512, 512)
    const float* bsh = (const float*)d_in[2];   // (512,)
    const float* W1  = (const float*)d_in[3];   // (32, 512, 512)
    const float* b1  = (const float*)d_in[4];   // (32, 512)
    const float* W2  = (const float*)d_in[5];   // (32, 512, 32)
    const float* b2  = (const float*)d_in[6];   // (32, 32)
    const int*   route = (const int*)d_in[7];   // (32,)
    float* out = (float*)d_out;                 // (4096, 32, 32)

    __half *x0h, *x1h, *hh, *wshT, *w1T, *w2T;
    cudaGetSymbolAddress((void**)&x0h,  g_x0h);
    cudaGetSymbolAddress((void**)&x1h,  g_x1h);
    cudaGetSymbolAddress((void**)&hh,   g_hh);
    cudaGetSymbolAddress((void**)&wshT, g_wshT);
    cudaGetSymbolAddress((void**)&w1T,  g_w1T);
    cudaGetSymbolAddress((void**)&w2T,  g_w2T);

    // Pre-passes: x0 -> fp16; weights -> transposed fp16.
    cvt_f32_f16_kernel<<<(67108864 / 8 + 255) / 256, 256>>>(x0, x0h, 67108864 / 8);
    dim3 tb(32, 8);
    transpose_h_kernel<<<dim3(16, 16, 1),  tb>>>(Wsh, wshT, 512, 512);
    transpose_h_kernel<<<dim3(16, 16, 32), tb>>>(W1,  w1T,  512, 512);
    transpose_h_kernel<<<dim3(1,  16, 32), tb>>>(W2,  w2T,  512, 32);

    constexpr int SMEM_BIG   = 128 + 3 * (128 + 256) * 128;  // ~147.6 KB
    constexpr int SMEM_SMALL = 128 + 3 * (128 + 32)  * 128;  // ~61.6 KB

    auto* kBig1 = hgemm<128, 256, 64, 64, 256, 3, true,  false, true>;
    auto* kBig2 = hgemm<128, 256, 64, 64, 256, 3, true,  true,  true>;
    auto* kSm3  = hgemm<128, 32,  32, 32, 128, 3, false, true,  false>;
    cudaFuncSetAttribute(kBig1, cudaFuncAttributeMaxDynamicSharedMemorySize, SMEM_BIG);
    cudaFuncSetAttribute(kBig2, cudaFuncAttributeMaxDynamicSharedMemorySize, SMEM_BIG);
    cudaFuncSetAttribute(kSm3,  cudaFuncAttributeMaxDynamicSharedMemorySize, SMEM_SMALL);

    // L1: x1h = relu(x0h @ Wsh + bsh)  M=131072 N=512 K=512
    kBig1<<<dim3(2, 1024, 1), 256, SMEM_BIG>>>(
        x0h, 0, 512, wshT, bsh, nullptr, x1h, 0, 512, 512, 512);

    // L2: hh[:,a,:] = relu(x1h[:,a,:] @ W1[route[a]] + b1[route[a]])
    kBig2<<<dim3(2, 32, 32), 256, SMEM_BIG>>>(
        x1h, 512, 32 * 512, w1T, b1, route, hh, 512, 32 * 512, 512, 512);

    // L3: y[:,a,:] = hh[:,a,:] @ W2[route[a]] + b2[route[a]]
    kSm3<<<dim3(1, 32, 32), 128, SMEM_SMALL>>>(
        hh, 512, 32 * 512, w2T, b2, route, out, 32, 32 * 32, 32, 512);
}

// round 4
// speedup vs baseline: 2.3361x; 1.1330x over previous
#include <cuda_runtime.h>
#include <cuda_fp16.h>
#include <cstdint>

// ---------------------------------------------------------------------------
// DivTree fully-fused megakernel (fp16 mma.sync m16n8k16, f32 accum).
// One CTA = 64 batch-rows x 1 agent. All intermediates live in SMEM:
//   phase 0: x0 (f32, gmem) -> As (f16, smem, swizzled)         [64 x 512]
//   phase 1: x1s = relu(As @ WshT + bsh)    -> smem             [64 x 512]
//   phase 2: hs  = relu(x1s @ W1T[e] + b1)  -> smem (reuses As) [64 x 512]
//   phase 3: out = hs @ W2T[e] + b2         -> gmem f32         [64 x 32]
// Prepass (1 launch): transpose+f16 all weights. Total 2 launches.
// ---------------------------------------------------------------------------

// Scratch (allocation-free rule: __device__ globals).
__device__ __half g_wshT[262144];    // 512*512
__device__ __half g_w1T[8388608];    // 32*512*512
__device__ __half g_w2T[524288];     // 32*32*512

// ----------------------------- PTX helpers --------------------------------
__device__ __forceinline__ uint32_t smem_u32(const void* p) {
    uint32_t a;
    asm("{ .reg .u64 t; cvta.to.shared.u64 t, %1; cvt.u32.u64 %0, t; }"
        : "=r"(a) : "l"(p));
    return a;
}
__device__ __forceinline__ void cp_async16(uint32_t dst, const void* src) {
    asm volatile("cp.async.cg.shared.global [%0], [%1], 16;\n" :: "r"(dst), "l"(src));
}
__device__ __forceinline__ void cp_commit() { asm volatile("cp.async.commit_group;\n"); }
template<int N>
__device__ __forceinline__ void cp_wait_group() {
    asm volatile("cp.async.wait_group %0;\n" :: "n"(N));
}
__device__ __forceinline__ void ldsm_x4(uint32_t* r, uint32_t addr) {
    asm volatile("ldmatrix.sync.aligned.m8n8.x4.shared.b16 {%0,%1,%2,%3}, [%4];"
                 : "=r"(r[0]), "=r"(r[1]), "=r"(r[2]), "=r"(r[3]) : "r"(addr));
}
__device__ __forceinline__ void mma_f16(float* c, const uint32_t* a, const uint32_t* b) {
    asm volatile(
        "mma.sync.aligned.m16n8k16.row.col.f32.f16.f16.f32 "
        "{%0,%1,%2,%3}, {%4,%5,%6,%7}, {%8,%9}, {%0,%1,%2,%3};\n"
        : "+f"(c[0]), "+f"(c[1]), "+f"(c[2]), "+f"(c[3])
        : "r"(a[0]), "r"(a[1]), "r"(a[2]), "r"(a[3]), "r"(b[0]), "r"(b[1]));
}
__device__ __forceinline__ void sts32(uint32_t addr, uint32_t v) {
    asm volatile("st.shared.b32 [%0], %1;" :: "r"(addr), "r"(v) : "memory");
}
__device__ __forceinline__ void sts64(uint32_t addr, uint32_t v0, uint32_t v1) {
    asm volatile("st.shared.v2.b32 [%0], {%1, %2};" :: "r"(addr), "r"(v0), "r"(v1) : "memory");
}
__device__ __forceinline__ uint32_t h2u(__half2 h) { return *(uint32_t*)&h; }

// ------------- prepass: transpose + cvt ALL weights to fp16 ----------------
// z=0: Wsh(512x512); z in [1,32]: W1[z-1](512x512); z in [33,64]: W2[z-33](512x32)
__global__ void transpose_all_kernel(const float* __restrict__ Wsh,
                                     const float* __restrict__ W1,
                                     const float* __restrict__ W2,
                                     __half* __restrict__ wshT,
                                     __half* __restrict__ w1T,
                                     __half* __restrict__ w2T) {
    const int z = blockIdx.z;
    const float* W;
    __half* WT;
    int N;
    if (z == 0)       { W = Wsh;                                WT = wshT;                              N = 512; }
    else if (z <= 32) { W = W1 + (size_t)(z - 1) * 512 * 512;   WT = w1T + (size_t)(z - 1) * 512 * 512; N = 512; }
    else {
        if (blockIdx.x != 0) return;
        W = W2 + (size_t)(z - 33) * 512 * 32;
        WT = w2T + (size_t)(z - 33) * 32 * 512;
        N = 32;
    }
    __shared__ float t[32][33];
    const int k0 = blockIdx.y * 32;
    const int n0 = blockIdx.x * 32;
    const int tx = threadIdx.x, ty = threadIdx.y;
    #pragma unroll
    for (int i = 0; i < 32; i += 8)
        t[ty + i][tx] = W[(size_t)(k0 + ty + i) * N + n0 + tx];
    __syncthreads();
    #pragma unroll
    for (int i = 0; i < 32; i += 8)
        WT[(size_t)(n0 + ty + i) * 512 + k0 + tx] = __float2half_rn(t[tx][ty + i]);
}

// ------------------------------ megakernel ---------------------------------
// SMEM map (offsets from 1024-aligned base):
//   As : 0      .. 65536   8 kb-blocks x [64 rows x 128B], swizzled (also hs)
//   X1 : 65536  .. 131072  same layout
//   BS : 131072 .. 163840  two 16KB B-staging buffers
constexpr int MEGA_SMEM = 163840 + 1024;

__global__ void __launch_bounds__(256, 1)
divtree_mega(const float* __restrict__ x0,
             const __half* __restrict__ wshT, const float* __restrict__ bsh,
             const __half* __restrict__ w1T,  const float* __restrict__ b1,
             const __half* __restrict__ w2T,  const float* __restrict__ b2,
             const int* __restrict__ route,
             float* __restrict__ out)
{
    extern __shared__ char smraw[];
    const uint32_t base = (smem_u32(smraw) + 1023) & ~1023u;
    const uint32_t As = base;
    const uint32_t X1 = base + 65536;
    const uint32_t BS0 = base + 131072;
    const uint32_t BS1 = base + 147456;

    const int tid  = threadIdx.x;
    const int lane = tid & 31;
    const int wid  = tid >> 5;
    const int g    = lane >> 2;
    const int tg   = lane & 3;
    const uint32_t a_hb   = (uint32_t)(lane >> 4);
    const uint32_t b_cadd = (uint32_t)((lane >> 3) & 1);

    const int m0    = blockIdx.x * 64;
    const int agent = blockIdx.y;
    const int e     = __ldg(&route[agent]);

    // ---------------- phase 0: x0 f32 -> As f16 (swizzled kb blocks) --------
    {
        #pragma unroll
        for (int rr = 0; rr < 8; ++rr) {
            const int r = wid * 8 + rr;
            const float* src = x0 + ((size_t)(m0 + r) * 32 + agent) * 512;
            #pragma unroll
            for (int i = 0; i < 4; ++i) {
                const int d = i * 128 + lane * 4;
                const float4 f = *(const float4*)&src[d];
                const uint32_t u0 = h2u(__floats2half2_rn(f.x, f.y));
                const uint32_t u1 = h2u(__floats2half2_rn(f.z, f.w));
                const int kb = d >> 6, c = d & 63;
                const uint32_t addr = As + (uint32_t)kb * 8192 + (uint32_t)r * 128 +
                                      ((uint32_t)((c >> 3) ^ (r & 7)) << 4) + (uint32_t)(c & 7) * 2;
                sts64(addr, u0, u1);
            }
        }
    }
    __syncthreads();

    // ---------------- layers 1 & 2: [64x512] = relu([64x512]@[512x512]+b) ---
    // warp grid 2x4 (warp tile 32x32), N chunks of 128, K stages of 64 halves.
    auto layer512 = [&](uint32_t aBase, const __half* __restrict__ Bg,
                        const float* __restrict__ bias, uint32_t dBase) {
        const int warp_m = wid >> 2;       // 0..1
        const int warp_n = wid & 3;        // 0..3
        uint32_t aAddr[2], aXor[2];
        #pragma unroll
        for (int mi = 0; mi < 2; ++mi) {
            const int r = warp_m * 32 + mi * 16 + (lane & 15);
            aAddr[mi] = aBase + (uint32_t)r * 128;
            aXor[mi]  = (uint32_t)(r & 7) << 4;
        }
        uint32_t bOff[2], bXor[2];
        #pragma unroll
        for (int p = 0; p < 2; ++p) {
            const int rn = warp_n * 32 + p * 16 + (lane & 7) + ((lane >> 4) << 3);
            bOff[p] = (uint32_t)rn * 128;
            bXor[p] = (uint32_t)(rn & 7) << 4;
        }

        for (int nc = 0; nc < 4; ++nc) {
            const __half* Bn = Bg + (size_t)(nc * 128) * 512;
            float acc[2][4][4];
            #pragma unroll
            for (int mi = 0; mi < 2; ++mi)
                #pragma unroll
                for (int ni = 0; ni < 4; ++ni)
                    #pragma unroll
                    for (int q = 0; q < 4; ++q) acc[mi][ni][q] = 0.0f;

            // preload kt=0 into BS0
            #pragma unroll
            for (int i = 0; i < 4; ++i) {
                const int idx = i * 256 + tid;
                const int r = idx >> 3, c = idx & 7;
                cp_async16(BS0 + (uint32_t)r * 128 + ((uint32_t)(c ^ (r & 7)) << 4),
                           Bn + (size_t)r * 512 + c * 8);
            }
            cp_commit();

            for (int kt = 0; kt < 8; ++kt) {
                const uint32_t cur = (kt & 1) ? BS1 : BS0;
                if (kt < 7) {
                    const uint32_t nxt = (kt & 1) ? BS0 : BS1;
                    #pragma unroll
                    for (int i = 0; i < 4; ++i) {
                        const int idx = i * 256 + tid;
                        const int r = idx >> 3, c = idx & 7;
                        cp_async16(nxt + (uint32_t)r * 128 + ((uint32_t)(c ^ (r & 7)) << 4),
                                   Bn + (size_t)r * 512 + (kt + 1) * 64 + c * 8);
                    }
                    cp_commit();
                    cp_wait_group<1>();
                } else {
                    cp_wait_group<0>();
                }
                __syncthreads();

                #pragma unroll
                for (int ks = 0; ks < 4; ++ks) {
                    uint32_t af[2][4], bf[2][4];
                    #pragma unroll
                    for (int mi = 0; mi < 2; ++mi)
                        ldsm_x4(af[mi], aAddr[mi] + (uint32_t)kt * 8192 +
                                        ((((uint32_t)(2 * ks) + a_hb) << 4) ^ aXor[mi]));
                    #pragma unroll
                    for (int p = 0; p < 2; ++p)
                        ldsm_x4(bf[p], cur + bOff[p] +
                                       ((((uint32_t)(2 * ks) + b_cadd) << 4) ^ bXor[p]));
                    #pragma unroll
                    for (int mi = 0; mi < 2; ++mi)
                        #pragma unroll
                        for (int ni = 0; ni < 4; ++ni)
                            mma_f16(acc[mi][ni], af[mi], &bf[ni >> 1][(ni & 1) * 2]);
                }
                __syncthreads();
            }

            // epilogue: bias + relu + cvt -> dBase (swizzled f16)
            #pragma unroll
            for (int mi = 0; mi < 2; ++mi) {
                #pragma unroll
                for (int ni = 0; ni < 4; ++ni) {
                    const int row = warp_m * 32 + mi * 16 + g;
                    const int cg  = nc * 128 + warp_n * 32 + ni * 8 + tg * 2;
                    const float2 bv = *(const float2*)&bias[cg];
                    const float v0 = fmaxf(acc[mi][ni][0] + bv.x, 0.f);
                    const float v1 = fmaxf(acc[mi][ni][1] + bv.y, 0.f);
                    const float v2 = fmaxf(acc[mi][ni][2] + bv.x, 0.f);
                    const float v3 = fmaxf(acc[mi][ni][3] + bv.y, 0.f);
                    const int kb = cg >> 6, c = cg & 63;
                    const uint32_t a0 = dBase + (uint32_t)kb * 8192 + (uint32_t)row * 128 +
                                        ((uint32_t)((c >> 3) ^ (row & 7)) << 4) + (uint32_t)(c & 7) * 2;
                    sts32(a0,        h2u(__floats2half2_rn(v0, v1)));
                    sts32(a0 + 1024, h2u(__floats2half2_rn(v2, v3)));   // row+8
                }
            }
        }
    };

    layer512(As, wshT,                         bsh,             X1);   // L1
    layer512(X1, w1T + (size_t)e * 512 * 512,  b1 + e * 512,    As);   // L2 (hs -> As)

    // ---------------- phase 3: out[64x32] = hs @ W2T[e] + b2 ----------------
    {
        const int warp_m3 = wid >> 1;      // 0..3
        const int warp_n3 = wid & 1;       // 0..1
        const int ra = warp_m3 * 16 + (lane & 15);
        const uint32_t aA3 = As + (uint32_t)ra * 128;
        const uint32_t aX3 = (uint32_t)(ra & 7) << 4;
        const int rn = warp_n3 * 16 + (lane & 7) + ((lane >> 4) << 3);
        const uint32_t bO3 = (uint32_t)rn * 128;
        const uint32_t bX3 = (uint32_t)(rn & 7) << 4;
        const __half* B3 = w2T + (size_t)e * 32 * 512;

        float acc[2][4];
        #pragma unroll
        for (int ni = 0; ni < 2; ++ni)
            #pragma unroll
            for (int q = 0; q < 4; ++q) acc[ni][q] = 0.0f;

        // preload kt=0 (32 rows x 8 chunks = 256 = one per thread)
        {
            const int r = tid >> 3, c = tid & 7;
            cp_async16(BS0 + (uint32_t)r * 128 + ((uint32_t)(c ^ (r & 7)) << 4),
                       B3 + (size_t)r * 512 + c * 8);
            cp_commit();
        }
        for (int kt = 0; kt < 8; ++kt) {
            const uint32_t cur = (kt & 1) ? BS1 : BS0;
            if (kt < 7) {
                const uint32_t nxt = (kt & 1) ? BS0 : BS1;
                const int r = tid >> 3, c = tid & 7;
                cp_async16(nxt + (uint32_t)r * 128 + ((uint32_t)(c ^ (r & 7)) << 4),
                           B3 + (size_t)r * 512 + (kt + 1) * 64 + c * 8);
                cp_commit();
                cp_wait_group<1>();
            } else {
                cp_wait_group<0>();
            }
            __syncthreads();

            #pragma unroll
            for (int ks = 0; ks < 4; ++ks) {
                uint32_t af[4], bf[4];
                ldsm_x4(af, aA3 + (uint32_t)kt * 8192 +
                            ((((uint32_t)(2 * ks) + a_hb) << 4) ^ aX3));
                ldsm_x4(bf, cur + bO3 +
                            ((((uint32_t)(2 * ks) + b_cadd) << 4) ^ bX3));
                mma_f16(acc[0], af, &bf[0]);
                mma_f16(acc[1], af, &bf[2]);
            }
            __syncthreads();
        }

        #pragma unroll
        for (int ni = 0; ni < 2; ++ni) {
            const int row = m0 + warp_m3 * 16 + g;
            const int col = warp_n3 * 16 + ni * 8 + tg * 2;
            const float2 bv = *(const float2*)&b2[e * 32 + col];
            const float v0 = acc[ni][0] + bv.x;
            const float v1 = acc[ni][1] + bv.y;
            const float v2 = acc[ni][2] + bv.x;
            const float v3 = acc[ni][3] + bv.y;
            *(float2*)&out[((size_t)row * 32 + agent) * 32 + col]       = make_float2(v0, v1);
            *(float2*)&out[((size_t)(row + 8) * 32 + agent) * 32 + col] = make_float2(v2, v3);
        }
    }
}

// ------------------------------- launch ------------------------------------
extern "C" void kernel_launch(void* const* d_in, const int* in_sizes, int n_in,
                              void* d_out, int out_size) {
    (void)in_sizes; (void)n_in; (void)out_size;
    const float* x0  = (const float*)d_in[0];   // (4096, 32, 512)
    const float* Wsh = (const float*)d_in[1];   // (512, 512)
    const float* bsh = (const float*)d_in[2];   // (512,)
    const float* W1  = (const float*)d_in[3];   // (32, 512, 512)
    const float* b1  = (const float*)d_in[4];   // (32, 512)
    const float* W2  = (const float*)d_in[5];   // (32, 512, 32)
    const float* b2  = (const float*)d_in[6];   // (32, 32)
    const int*   route = (const int*)d_in[7];   // (32,)
    float* out = (float*)d_out;                 // (4096, 32, 32)

    __half *wshT, *w1T, *w2T;
    cudaGetSymbolAddress((void**)&wshT, g_wshT);
    cudaGetSymbolAddress((void**)&w1T,  g_w1T);
    cudaGetSymbolAddress((void**)&w2T,  g_w2T);

    cudaFuncSetAttribute(divtree_mega,
                         cudaFuncAttributeMaxDynamicSharedMemorySize, MEGA_SMEM);

    // Launch 1: transpose + f16 all weights.
    transpose_all_kernel<<<dim3(16, 16, 65), dim3(32, 8)>>>(Wsh, W1, W2, wshT, w1T, w2T);

    // Launch 2: fused 3-layer megakernel. Grid: 64 m-tiles x 32 agents.
    divtree_mega<<<dim3(64, 32), 256, MEGA_SMEM>>>(
        x0, wshT, bsh, w1T, b1, w2T, b2, route, out);
}